// round 1
// baseline (speedup 1.0000x reference)
#include <cuda_runtime.h>

// Path signature, depth 3. path: (32, 128, 48) fp32, row-major.
// Output per batch: [level1 (48) | level2 (2304) | level3 (110592)] = 112944 floats.
//
// Recurrences per increment v_t = path[t+1]-path[t], with S1prev = path[t]-path[0]:
//   S2[i,j] += (S1prev[i] + 0.5*v[i]) * v[j]
//   S3[i,j,k] += v[k] * ( S2prev[i,j] + (0.5*S1prev[i] + v[i]/6) * v[j] )
// Block (i, b) owns the 48x48 (j,k) tile of S3 in registers (4x4 per thread,
// 144 threads), plus the 48-wide S2 row recurrence in shared memory.

#define NB     32
#define LPATH  128
#define C      48
#define NSTEPS (LPATH - 1)
#define LVL2   (C * C)
#define LVL3   (C * C * C)
#define STR    (C + LVL2 + LVL3)   // 112944
#define OFF2   C                   // 48
#define OFF3   (C + LVL2)          // 2352

__global__ __launch_bounds__(144, 8)
void sig_depth3_kernel(const float* __restrict__ path, float* __restrict__ out)
{
    const int i   = blockIdx.x;   // 0..47  (first tensor index of level 2/3)
    const int b   = blockIdx.y;   // 0..31  (batch)
    const int tid = threadIdx.x;  // 0..143

    __shared__ __align__(16) float sh_S2[C];
    __shared__ __align__(16) float sh_v[2][C];
    __shared__ __align__(16) float sh_w[2][C];

    const float* pb = path + (size_t)b * LPATH * C;

    // 4x4 register tile of S3[i, j0:j0+4, k0:k0+4]
    float acc[4][4];
#pragma unroll
    for (int jj = 0; jj < 4; ++jj)
#pragma unroll
        for (int kk = 0; kk < 4; ++kk) acc[jj][kk] = 0.0f;

    const int jt = tid / 12;      // 0..11
    const int kt = tid % 12;      // 0..11
    const int j0 = jt * 4;
    const int k0 = kt * 4;

    // Phase-A state (threads 0..47 only): carried path values.
    float p_j = 0.0f, p_i = 0.0f, p_i0 = 0.0f;
    if (tid < C) {
        sh_S2[tid] = 0.0f;
        p_j  = pb[tid];        // path[b][0][tid]
        p_i0 = pb[i];          // path[b][0][i]
        p_i  = p_i0;
    }
    // No sync needed before the first iteration: phase B only reads after the
    // in-loop barrier, which orders it after phase A of the same step.

    for (int t = 0; t < NSTEPS; ++t) {
        const int buf = t & 1;
        if (tid < C) {
            const float pn_j = pb[(t + 1) * C + tid];  // coalesced row
            const float pn_i = pb[(t + 1) * C + i];    // warp-broadcast (L1 hit)
            const float v_j  = pn_j - p_j;
            const float v_i  = pn_i - p_i;
            const float s1_i = p_i - p_i0;
            sh_v[buf][tid] = v_j;
            sh_w[buf][tid] = sh_S2[tid] + (0.5f * s1_i + (1.0f / 6.0f) * v_i) * v_j;
            sh_S2[tid]    += (s1_i + 0.5f * v_i) * v_j;   // uses S2prev in w above
            p_j = pn_j;
            p_i = pn_i;
        }
        __syncthreads();
        // Double-buffered: phase A of step t+1 writes buf^1 while stragglers of
        // step t still read buf; buffer buf is only rewritten at step t+2, which
        // every thread reaches only after passing the barrier of step t+1.
        const float4 wv = *(const float4*)&sh_w[buf][j0];
        const float4 vv = *(const float4*)&sh_v[buf][k0];
        const float w4[4] = { wv.x, wv.y, wv.z, wv.w };
        const float v4[4] = { vv.x, vv.y, vv.z, vv.w };
#pragma unroll
        for (int jj = 0; jj < 4; ++jj)
#pragma unroll
            for (int kk = 0; kk < 4; ++kk)
                acc[jj][kk] = fmaf(w4[jj], v4[kk], acc[jj][kk]);
    }

    // ---- Epilogue ----
    float* ob = out + (size_t)b * STR;

    // Level 3: 16 values per thread, float4 stores (all offsets 16B-aligned).
    float* o3 = ob + OFF3 + i * LVL2;
#pragma unroll
    for (int jj = 0; jj < 4; ++jj) {
        float4 r = make_float4(acc[jj][0], acc[jj][1], acc[jj][2], acc[jj][3]);
        *(float4*)&o3[(j0 + jj) * C + k0] = r;
    }

    if (tid < C) {
        // Level 2 row i (thread owns sh_S2[tid]; no cross-thread read).
        ob[OFF2 + i * C + tid] = sh_S2[tid];
        // Level 1 (one block per batch writes it).
        if (i == 0) {
            // p_j now holds path[b][127][tid]
            ob[tid] = p_j - pb[tid];
        }
    }
}

extern "C" void kernel_launch(void* const* d_in, const int* in_sizes, int n_in,
                              void* d_out, int out_size)
{
    (void)in_sizes; (void)n_in; (void)out_size;
    const float* path = (const float*)d_in[0];
    float* out = (float*)d_out;
    dim3 grid(C, NB);      // (i, batch) = (48, 32)
    dim3 block(144);
    sig_depth3_kernel<<<grid, block>>>(path, out);
}

// round 2
// speedup vs baseline: 1.7421x; 1.7421x over previous
#include <cuda_runtime.h>

// Path signature, depth 3. path: (32, 128, 48) fp32, row-major.
// Output per batch: [level1 (48) | level2 (2304) | level3 (110592)] = 112944 floats.
//
// S3[i,j,k] = sum_t w[i][t][j] * v[t][k], where
//   v[t][j]  = path[t+1][j] - path[t][j]
//   w[i][t][j] = S2prev[i][j] + (0.5*S1prev[i] + v[t][i]/6) * v[t][j]
//   S2[i][j] += (S1prev[i] + 0.5*v[t][i]) * v[t][j]
// Block (i, b): 48x48 (j,k) tile of S3 in registers (4x4 per thread, 144 thr).
// Reduction chunked by T=8 steps: phase A fills sh_v/sh_w for 8 steps (threads
// 0..47, 8-deep FMA chain per thread), one barrier, phase B does 128 FMAs.

#define NB     32
#define LPATH  128
#define C      48
#define NSTEPS (LPATH - 1)          // 127
#define LVL2   (C * C)
#define LVL3   (C * C * C)
#define STR    (C + LVL2 + LVL3)    // 112944
#define OFF2   C
#define OFF3   (C + LVL2)
#define TCH    8

template<int T>
__device__ __forceinline__ void do_chunk(
    const float* __restrict__ pb, int base_t, int i, int tid,
    float (&acc)[4][4], int j0, int k0,
    float& p_j, float& p_i, float p0_i, float& S2,
    float (*sh_v)[C], float (*sh_w)[C])
{
    // ---- Phase A: threads 0..47 produce v/w for T steps ----
    if (tid < C) {
#pragma unroll
        for (int t = 0; t < T; ++t) {
            const float pn_j = pb[(base_t + t + 1) * C + tid];  // coalesced row
            const float pn_i = pb[(base_t + t + 1) * C + i];    // broadcast addr
            const float v_j = pn_j - p_j;
            const float v_i = pn_i - p_i;
            const float s1  = p_i - p0_i;
            sh_v[t][tid] = v_j;
            sh_w[t][tid] = fmaf(fmaf(1.0f / 6.0f, v_i, 0.5f * s1), v_j, S2);
            S2 = fmaf(fmaf(0.5f, v_i, s1), v_j, S2);
            p_j = pn_j;
            p_i = pn_i;
        }
    }
    __syncthreads();
    // ---- Phase B: all 144 threads, T rank-1 updates of the 4x4 tile ----
#pragma unroll
    for (int t = 0; t < T; ++t) {
        const float4 wv = *(const float4*)&sh_w[t][j0];
        const float4 vv = *(const float4*)&sh_v[t][k0];
        const float w4[4] = { wv.x, wv.y, wv.z, wv.w };
        const float v4[4] = { vv.x, vv.y, vv.z, vv.w };
#pragma unroll
        for (int jj = 0; jj < 4; ++jj)
#pragma unroll
            for (int kk = 0; kk < 4; ++kk)
                acc[jj][kk] = fmaf(w4[jj], v4[kk], acc[jj][kk]);
    }
    __syncthreads();   // protect sh_v/sh_w before next chunk's phase A
}

__global__ __launch_bounds__(144, 8)
void sig_depth3_kernel(const float* __restrict__ path, float* __restrict__ out)
{
    const int i   = blockIdx.x;   // 0..47  first tensor index
    const int b   = blockIdx.y;   // 0..31  batch
    const int tid = threadIdx.x;  // 0..143

    __shared__ __align__(16) float sh_v[TCH][C];
    __shared__ __align__(16) float sh_w[TCH][C];

    const float* pb = path + (size_t)b * LPATH * C;

    float acc[4][4];
#pragma unroll
    for (int jj = 0; jj < 4; ++jj)
#pragma unroll
        for (int kk = 0; kk < 4; ++kk) acc[jj][kk] = 0.0f;

    const int j0 = (tid / 12) * 4;
    const int k0 = (tid % 12) * 4;

    // Phase-A carried state (threads 0..47)
    float p_j = 0.0f, p_i = 0.0f, p0_i = 0.0f, S2 = 0.0f;
    if (tid < C) {
        p_j  = pb[tid];
        p0_i = pb[i];
        p_i  = p0_i;
    }

    int base_t = 0;
    for (int ch = 0; ch < 15; ++ch) {    // 15 full chunks of 8 = 120 steps
        do_chunk<TCH>(pb, base_t, i, tid, acc, j0, k0, p_j, p_i, p0_i, S2,
                      sh_v, sh_w);
        base_t += TCH;
    }
    do_chunk<NSTEPS - 15 * TCH>(pb, base_t, i, tid, acc, j0, k0,   // tail: 7
                                p_j, p_i, p0_i, S2, sh_v, sh_w);

    // ---- Epilogue ----
    float* ob = out + (size_t)b * STR;

    float* o3 = ob + OFF3 + i * LVL2;
#pragma unroll
    for (int jj = 0; jj < 4; ++jj) {
        float4 r = make_float4(acc[jj][0], acc[jj][1], acc[jj][2], acc[jj][3]);
        *(float4*)&o3[(j0 + jj) * C + k0] = r;
    }

    if (tid < C) {
        ob[OFF2 + i * C + tid] = S2;          // level 2, row i
        if (i == 0) {
            // p_j now holds path[b][127][tid]
            ob[tid] = p_j - pb[tid];          // level 1
        }
    }
}

extern "C" void kernel_launch(void* const* d_in, const int* in_sizes, int n_in,
                              void* d_out, int out_size)
{
    (void)in_sizes; (void)n_in; (void)out_size;
    const float* path = (const float*)d_in[0];
    float* out = (float*)d_out;
    dim3 grid(C, NB);
    dim3 block(144);
    sig_depth3_kernel<<<grid, block>>>(path, out);
}

// round 3
// speedup vs baseline: 1.9200x; 1.1021x over previous
#include <cuda_runtime.h>

// Path signature, depth 3. path: (32, 128, 48) fp32, row-major.
// Output per batch: [level1 (48) | level2 (2304) | level3 (110592)] = 112944.
//
// S3[i,j,k] = sum_t w[i][t][j] * v[t][k]
//   v[t][j]    = path[t+1][j] - path[t][j]
//   w[i][t][j] = S2prev[i][j] + (0.5*S1prev[i] + v[t][i]/6) * v[t][j]
//   S2[i][j]  += (S1prev[i] + 0.5*v[t][i]) * v[t][j]
//
// Block (bx, b) owns TWO i-planes (i0 = 2bx, i1 = 2bx+1): two 48x48 (j,k)
// tiles in registers (2 x 4x4 per thread, 144 threads). sh_v is shared
// between both planes -> 1.5 B LDS per lane-FMA. Reduction chunked by T=8
// steps; double-buffered v/w gives ONE barrier per chunk.

#define NB     32
#define LPATH  128
#define C      48
#define NSTEPS (LPATH - 1)          // 127
#define LVL2   (C * C)
#define LVL3   (C * C * C)
#define STR    (C + LVL2 + LVL3)    // 112944
#define OFF2   C
#define OFF3   (C + LVL2)
#define TCH    8

template<int T>
__device__ __forceinline__ void do_chunk(
    const float* __restrict__ pb, int base_t, int buf, int i_r, int r, int jj,
    int tid, float (&acc0)[4][4], float (&acc1)[4][4], int j0, int k0,
    float& p_j, float& p_i, float p0_i, float& S2,
    float (*sh_v)[TCH][C], float (*sh_w)[2][TCH][C])
{
    // ---- Phase A: threads 0..95 (3 warps); group r produces w-row for i_r,
    //      group 0 also publishes v. ----
    if (tid < 2 * C) {
#pragma unroll
        for (int t = 0; t < T; ++t) {
            const float pn_j = pb[(base_t + t + 1) * C + jj];  // coalesced
            const float pn_i = pb[(base_t + t + 1) * C + i_r]; // broadcast
            const float v_j = pn_j - p_j;
            const float v_i = pn_i - p_i;
            const float s1  = p_i - p0_i;
            if (r == 0) sh_v[buf][t][jj] = v_j;
            sh_w[buf][r][t][jj] = fmaf(fmaf(1.0f / 6.0f, v_i, 0.5f * s1), v_j, S2);
            S2 = fmaf(fmaf(0.5f, v_i, s1), v_j, S2);
            p_j = pn_j;
            p_i = pn_i;
        }
    }
    __syncthreads();
    // Safe with double buffering and ONE barrier per chunk: every thread
    // executes phase B of chunk c before arriving at the barrier of chunk
    // c+1, so when producers start phase A of chunk c+2 (same buffer as c),
    // all readers of chunk c are provably done.

    // ---- Phase B: all 144 threads, T rank-1 updates of both 4x4 tiles ----
#pragma unroll
    for (int t = 0; t < T; ++t) {
        const float4 w0 = *(const float4*)&sh_w[buf][0][t][j0];
        const float4 w1 = *(const float4*)&sh_w[buf][1][t][j0];
        const float4 vv = *(const float4*)&sh_v[buf][t][k0];
        const float wa[4] = { w0.x, w0.y, w0.z, w0.w };
        const float wb[4] = { w1.x, w1.y, w1.z, w1.w };
        const float v4[4] = { vv.x, vv.y, vv.z, vv.w };
#pragma unroll
        for (int jx = 0; jx < 4; ++jx)
#pragma unroll
            for (int kx = 0; kx < 4; ++kx) {
                acc0[jx][kx] = fmaf(wa[jx], v4[kx], acc0[jx][kx]);
                acc1[jx][kx] = fmaf(wb[jx], v4[kx], acc1[jx][kx]);
            }
    }
}

__global__ __launch_bounds__(144, 6)
void sig_depth3_kernel(const float* __restrict__ path, float* __restrict__ out)
{
    const int bx  = blockIdx.x;   // 0..23 -> i0 = 2bx, i1 = 2bx+1
    const int b   = blockIdx.y;   // 0..31
    const int tid = threadIdx.x;  // 0..143

    __shared__ __align__(16) float sh_v[2][TCH][C];
    __shared__ __align__(16) float sh_w[2][2][TCH][C];

    const float* pb = path + (size_t)b * LPATH * C;

    float acc0[4][4], acc1[4][4];
#pragma unroll
    for (int jx = 0; jx < 4; ++jx)
#pragma unroll
        for (int kx = 0; kx < 4; ++kx) { acc0[jx][kx] = 0.0f; acc1[jx][kx] = 0.0f; }

    const int j0 = (tid / 12) * 4;
    const int k0 = (tid % 12) * 4;

    // Phase-A identity (threads 0..95): group r handles i_r = 2bx + r.
    const int r  = (tid < C) ? 0 : 1;
    const int jj = tid - r * C;              // 0..47 within group
    const int i_r = 2 * bx + r;

    float p_j = 0.0f, p_i = 0.0f, p0_i = 0.0f, S2 = 0.0f;
    if (tid < 2 * C) {
        p_j  = pb[jj];
        p0_i = pb[i_r];
        p_i  = p0_i;
    }

    int base_t = 0;
#pragma unroll 1
    for (int ch = 0; ch < 15; ++ch) {        // 15 chunks of 8 = 120 steps
        do_chunk<TCH>(pb, base_t, ch & 1, i_r, r, jj, tid, acc0, acc1,
                      j0, k0, p_j, p_i, p0_i, S2, sh_v, sh_w);
        base_t += TCH;
    }
    do_chunk<NSTEPS - 15 * TCH>(pb, base_t, 15 & 1, i_r, r, jj, tid,  // tail 7
                                acc0, acc1, j0, k0, p_j, p_i, p0_i, S2,
                                sh_v, sh_w);

    // ---- Epilogue ----
    float* ob = out + (size_t)b * STR;

    float* o30 = ob + OFF3 + (size_t)(2 * bx)     * LVL2;
    float* o31 = ob + OFF3 + (size_t)(2 * bx + 1) * LVL2;
#pragma unroll
    for (int jx = 0; jx < 4; ++jx) {
        *(float4*)&o30[(j0 + jx) * C + k0] =
            make_float4(acc0[jx][0], acc0[jx][1], acc0[jx][2], acc0[jx][3]);
        *(float4*)&o31[(j0 + jx) * C + k0] =
            make_float4(acc1[jx][0], acc1[jx][1], acc1[jx][2], acc1[jx][3]);
    }

    if (tid < 2 * C) {
        ob[OFF2 + i_r * C + jj] = S2;            // level 2, rows i0/i1
        if (bx == 0 && r == 0) {
            // p_j now holds path[b][127][jj]
            ob[jj] = p_j - pb[jj];               // level 1
        }
    }
}

extern "C" void kernel_launch(void* const* d_in, const int* in_sizes, int n_in,
                              void* d_out, int out_size)
{
    (void)in_sizes; (void)n_in; (void)out_size;
    const float* path = (const float*)d_in[0];
    float* out = (float*)d_out;
    dim3 grid(C / 2, NB);   // (i-pairs, batch) = (24, 32)
    dim3 block(144);
    sig_depth3_kernel<<<grid, block>>>(path, out);
}